// round 13
// baseline (speedup 1.0000x reference)
#include <cuda_runtime.h>

// AttributeBiasLoss — exact emulation of the reference's sequential fp32
// segment_sum (validated: rel_err 4.4e-6).
//   kA : per-chunk bin counts only (attrs, 64MB) + flag reset
//   kB : block-per-bin parallel scan of chunk counts -> [chunk][bin]
//   kB2: bin bases + ticket resets
//   kSF: SM-partitioned fused scatter + fold, occ 2 (64-reg budget).
//        Scatter computes the per-node sigmoid mean inline (same fp32 op
//        order as reference). Fold chain = 4-stage register pipeline
//        (LDS issued 3 groups / 96cyc ahead), FADD order bit-exact.
//   k4 : fp32 means/diffs, final reduction

#define MAX_B      2097152
#define CHUNK      256
#define MAX_NCHUNK (MAX_B / CHUNK)   // 8192
#define NBIN       128
#define FOLD_SMS   64                // SMs reserved for fold chains
#define SWARPS     16                // warps per block
#define KSF_GRID   304               // 2 blocks/SM resident (occ 2)
#define FOLD_BUF   4096              // floats per double-buffer half (16KB)

__device__ float    g_sorted[MAX_B * 8];
__device__ unsigned g_counts[NBIN * MAX_NCHUNK];    // [bin][chunk]
__device__ unsigned g_chunkoff[MAX_NCHUNK * NBIN];  // [chunk][bin], bin-relative
__device__ unsigned g_flag[MAX_NCHUNK];
__device__ unsigned g_ticket;                        // scatter chunk ticket
__device__ unsigned g_fold_ticket;                   // fold bin ticket
__device__ unsigned g_bintotal[NBIN];
__device__ unsigned g_binbase[NBIN];
__device__ float    g_binmean[NBIN];

__device__ __forceinline__ float ref_sigmoid(float x) {
    float e = expf(-x);
    return __fdiv_rn(1.0f, __fadd_rn(1.0f, e));
}
__device__ __forceinline__ void st_release_flag(unsigned* p, unsigned v) {
    asm volatile("st.release.gpu.global.b32 [%0], %1;" :: "l"(p), "r"(v) : "memory");
}
__device__ __forceinline__ unsigned ld_acquire_flag(const unsigned* p) {
    unsigned v;
    asm volatile("ld.acquire.gpu.global.b32 %0, [%1];" : "=r"(v) : "l"(p) : "memory");
    return v;
}

// ---------------- kA: per-chunk counts + flag reset --------------------------
__global__ void __launch_bounds__(256) kA_count(const int* __restrict__ attrs, int B)
{
    __shared__ unsigned cnt[NBIN];
    int tid = threadIdx.x;
    if (tid < NBIN) cnt[tid] = 0;
    if (tid == 0) g_flag[blockIdx.x] = 0;
    __syncthreads();

    int r = blockIdx.x * CHUNK + tid;
    if (r < B) {
        const int4* a = reinterpret_cast<const int4*>(attrs + (size_t)r * 8);
        int4 a0 = __ldg(a), a1 = __ldg(a + 1);
        atomicAdd(&cnt[  0 + a0.x], 1u);
        atomicAdd(&cnt[ 16 + a0.y], 1u);
        atomicAdd(&cnt[ 32 + a0.z], 1u);
        atomicAdd(&cnt[ 48 + a0.w], 1u);
        atomicAdd(&cnt[ 64 + a1.x], 1u);
        atomicAdd(&cnt[ 80 + a1.y], 1u);
        atomicAdd(&cnt[ 96 + a1.z], 1u);
        atomicAdd(&cnt[112 + a1.w], 1u);
    }
    __syncthreads();
    if (tid < NBIN)
        g_counts[(size_t)tid * MAX_NCHUNK + blockIdx.x] = cnt[tid];
}

// ---------------- kB: block-per-bin parallel scan ---------------------------
__global__ void __launch_bounds__(128) kB_scan(int nchunk) {
    int bin  = blockIdx.x;
    int t    = threadIdx.x;
    int lane = t & 31, wid = t >> 5;
    const unsigned* src = &g_counts[(size_t)bin * MAX_NCHUNK];
    __shared__ unsigned wsum[4];

    unsigned run = 0;
    for (int c0 = 0; c0 < nchunk; c0 += 128) {
        int c = c0 + t;
        unsigned v = (c < nchunk) ? src[c] : 0u;
        unsigned x = v;
        #pragma unroll
        for (int o = 1; o < 32; o <<= 1) {
            unsigned y = __shfl_up_sync(0xffffffffu, x, o);
            if (lane >= o) x += y;
        }
        if (lane == 31) wsum[wid] = x;
        __syncthreads();
        unsigned woff = 0;
        #pragma unroll
        for (int w = 0; w < 4; w++) if (w < wid) woff += wsum[w];
        if (c < nchunk)
            g_chunkoff[(size_t)c * NBIN + bin] = run + woff + x - v;
        unsigned btot = wsum[0] + wsum[1] + wsum[2] + wsum[3];
        __syncthreads();
        run += btot;
    }
    if (t == 0) g_bintotal[bin] = run;
}

// ---------------- kB2: bin bases + ticket resets -----------------------------
__global__ void __launch_bounds__(128) kB2_base() {
    int t    = threadIdx.x;
    int lane = t & 31, wid = t >> 5;
    __shared__ unsigned wsum[4];
    unsigned v = g_bintotal[t];
    unsigned x = v;
    #pragma unroll
    for (int o = 1; o < 32; o <<= 1) {
        unsigned y = __shfl_up_sync(0xffffffffu, x, o);
        if (lane >= o) x += y;
    }
    if (lane == 31) wsum[wid] = x;
    __syncthreads();
    unsigned woff = 0;
    #pragma unroll
    for (int w = 0; w < 4; w++) if (w < wid) woff += wsum[w];
    g_binbase[t] = woff + x - v;
    if (t == 0) { g_ticket = 0; g_fold_ticket = 0; }
}

// fold 8 values (two float4) into s, strict left-to-right fp32 order
#define FOLD8(A0, A1)                                          \
    do {                                                       \
        s = __fadd_rn(s, (A0).x); s = __fadd_rn(s, (A0).y);    \
        s = __fadd_rn(s, (A0).z); s = __fadd_rn(s, (A0).w);    \
        s = __fadd_rn(s, (A1).x); s = __fadd_rn(s, (A1).y);    \
        s = __fadd_rn(s, (A1).z); s = __fadd_rn(s, (A1).w);    \
    } while (0)

// ---------------- fold: one bin, executed by a whole block -------------------
__device__ void fold_bin(int bin, int nchunk, float (*buf)[FOLD_BUF])
{
    int tid  = threadIdx.x;
    int wid  = tid >> 5;
    int lane = tid & 31;

    unsigned n    = g_bintotal[bin];
    unsigned base = g_binbase[bin];
    int rounds = (int)((n + FOLD_BUF - 1) / FOLD_BUF);

    unsigned watermark = 0, ready = 0;  // prefetch-warp state

    if (wid == 1 && rounds > 0) {
        unsigned need = min(n, (unsigned)FOLD_BUF);
        while (ready < need) {
            int c = (int)watermark + lane;
            unsigned f = (c < nchunk) ? ld_acquire_flag(&g_flag[c]) : 1u;
            unsigned ball = __ballot_sync(0xffffffffu, f != 0);
            unsigned adv  = (ball == 0xffffffffu) ? 32u : (unsigned)(__ffs(~ball) - 1);
            if (adv == 0) { __nanosleep(128); continue; }
            watermark += adv;
            if ((int)watermark >= nchunk) { ready = n; break; }
            ready = g_chunkoff[(size_t)watermark * NBIN + bin];
        }
        #pragma unroll
        for (int j = 0; j < FOLD_BUF / 32; j++)
            buf[0][j * 32 + lane] = g_sorted[base + j * 32 + lane];
    }
    __syncthreads();

    float s = 0.0f;
    for (int r = 0; r < rounds; r++) {
        if (wid == 1) {
            if (r + 1 < rounds) {
                unsigned need = min(n, (unsigned)(r + 2) * FOLD_BUF);
                while (ready < need) {
                    int c = (int)watermark + lane;
                    unsigned f = (c < nchunk) ? ld_acquire_flag(&g_flag[c]) : 1u;
                    unsigned ball = __ballot_sync(0xffffffffu, f != 0);
                    unsigned adv  = (ball == 0xffffffffu) ? 32u : (unsigned)(__ffs(~ball) - 1);
                    if (adv == 0) { __nanosleep(128); continue; }
                    watermark += adv;
                    if ((int)watermark >= nchunk) { ready = n; break; }
                    ready = g_chunkoff[(size_t)watermark * NBIN + bin];
                }
                unsigned o = base + (unsigned)(r + 1) * FOLD_BUF;
                float* dst = buf[(r + 1) & 1];
                #pragma unroll
                for (int j = 0; j < FOLD_BUF / 32; j++)
                    dst[j * 32 + lane] = g_sorted[o + j * 32 + lane];
            }
        } else if (tid == 0) {
            // bit-exact serial fp32 chain; 4-stage pipeline: LDS issued three
            // 8-elem groups (96 cyc) ahead of consumption, no in-loop branches.
            const float4* b4 = reinterpret_cast<const float4*>(buf[r & 1]);
            const float*  bf = buf[r & 1];
            int cnt = min(FOLD_BUF, (int)(n - (unsigned)r * FOLD_BUF));
            int groups = cnt >> 3;
            int g = 0;
            if (groups >= 3) {
                float4 A0 = b4[0], A1 = b4[1];
                float4 B0 = b4[2], B1 = b4[3];
                float4 C0 = b4[4], C1 = b4[5];
                for (; g + 3 < groups; g++) {
                    float4 D0 = b4[2 * g + 6], D1 = b4[2 * g + 7];
                    FOLD8(A0, A1);
                    A0 = B0; A1 = B1; B0 = C0; B1 = C1; C0 = D0; C1 = D1;
                }
                FOLD8(A0, A1); g++;
                FOLD8(B0, B1); g++;
                FOLD8(C0, C1); g++;
            }
            for (int i = g * 8; i < cnt; i++) s = __fadd_rn(s, bf[i]);
        }
        __syncthreads();
    }
    if (tid == 0)
        g_binmean[bin] = (n > 0) ? __fdiv_rn(s, (float)n) : 0.0f;
    __syncthreads();
}

// ---------------- kSF: SM-partitioned scatter + fold -------------------------
__global__ void __launch_bounds__(32 * SWARPS, 2) kSF(
    const float* __restrict__ pred, const int* __restrict__ attrs,
    int B, int nchunk)
{
    __shared__ union {
        unsigned soff[SWARPS][NBIN];
        float    buf[2][FOLD_BUF];
    } sm;
    __shared__ int s_ticket;

    int tid  = threadIdx.x;
    int wid  = tid >> 5;
    int lane = tid & 31;

    unsigned smid;
    asm("mov.u32 %0, %%smid;" : "=r"(smid));

    if (smid < FOLD_SMS) {
        // ------------------- fold SM: claim a bin, fold it -------------------
        if (tid == 0) s_ticket = (int)atomicAdd(&g_fold_ticket, 1u);
        __syncthreads();
        int bin = s_ticket;
        if (bin < NBIN) fold_bin(bin, nchunk, sm.buf);
        return;
    }

    // ------------------- scatter SM: ticket-ordered chunks -------------------
    {
        unsigned* off = sm.soff[wid];
        for (;;) {
            int chunk = 0;
            if (lane == 0) chunk = (int)atomicAdd(&g_ticket, 1u);
            chunk = __shfl_sync(0xffffffffu, chunk, 0);
            if (chunk >= nchunk) break;

            for (int i = lane; i < NBIN; i += 32)
                off[i] = g_binbase[i] + g_chunkoff[(size_t)chunk * NBIN + i];
            __syncwarp();

            int start = chunk * CHUNK;
            #pragma unroll 1
            for (int s = 0; s < CHUNK / 32; s++) {
                int  r   = start + s * 32 + lane;
                bool act = (r < B);
                float pn = 0.f;
                int v[8];
                if (act) {
                    const int4* ap = reinterpret_cast<const int4*>(attrs + (size_t)r * 8);
                    int4 a0 = __ldg(ap), a1 = __ldg(ap + 1);
                    v[0] = a0.x; v[1] = a0.y; v[2] = a0.z; v[3] = a0.w;
                    v[4] = a1.x; v[5] = a1.y; v[6] = a1.z; v[7] = a1.w;
                    // per-node mean of sigmoids, same fp32 op order as reference
                    const float4* pp = reinterpret_cast<const float4*>(pred + (size_t)r * 8);
                    float4 p0 = __ldg(pp), p1 = __ldg(pp + 1);
                    float t0 = ref_sigmoid(p0.x);
                    t0 = __fadd_rn(t0, ref_sigmoid(p0.y));
                    t0 = __fadd_rn(t0, ref_sigmoid(p0.z));
                    t0 = __fadd_rn(t0, ref_sigmoid(p0.w));
                    t0 = __fadd_rn(t0, ref_sigmoid(p1.x));
                    t0 = __fadd_rn(t0, ref_sigmoid(p1.y));
                    t0 = __fadd_rn(t0, ref_sigmoid(p1.z));
                    t0 = __fadd_rn(t0, ref_sigmoid(p1.w));
                    pn = __fmul_rn(t0, 0.125f);
                } else {
                    #pragma unroll
                    for (int a = 0; a < 8; a++) v[a] = 16;
                }
                #pragma unroll
                for (int a = 0; a < 8; a++) {
                    unsigned mask   = __match_any_sync(0xffffffffu, v[a]);
                    unsigned rank   = __popc(mask & ((1u << lane) - 1u));
                    int      leader = __ffs(mask) - 1;
                    unsigned old    = 0;
                    if (lane == leader && v[a] < 16) {
                        int bin = a * 16 + v[a];
                        old = off[bin];
                        off[bin] = old + __popc(mask);
                    }
                    old = __shfl_sync(0xffffffffu, old, leader);
                    if (act) g_sorted[old + rank] = pn;
                }
                __syncwarp();
            }
            __threadfence();
            __syncwarp();
            if (lane == 0) st_release_flag(&g_flag[chunk], 1u);
        }
    }
    __syncthreads();

    // -------- safety net: fold any bins nobody on a fold SM claimed ----------
    for (;;) {
        if (tid == 0) s_ticket = (int)atomicAdd(&g_fold_ticket, 1u);
        __syncthreads();
        int bin = s_ticket;
        if (bin >= NBIN) break;
        fold_bin(bin, nchunk, sm.buf);
        __syncthreads();
    }
}

// ---------------- k4: pairwise squared diffs --------------------------------
__global__ void __launch_bounds__(128) k4_final(float* __restrict__ out) {
    __shared__ float  m[NBIN];
    __shared__ int    pres[NBIN];
    __shared__ double sl[128];
    __shared__ int    sc[128];
    int t = threadIdx.x;
    m[t]    = g_binmean[t];
    pres[t] = (g_bintotal[t] > 0);
    __syncthreads();
    double loss = 0.0;
    int    ncmp = 0;
    for (int idx = t; idx < 8 * 256; idx += 128) {
        int aa = idx >> 8, i = (idx >> 4) & 15, j = idx & 15;
        if (j > i) {
            int bi = aa * 16 + i, bj = aa * 16 + j;
            if (pres[bi] && pres[bj]) {
                float d  = __fsub_rn(m[bi], m[bj]);
                float dd = __fmul_rn(d, d);
                loss += (double)dd;
                ncmp += 1;
            }
        }
    }
    sl[t] = loss; sc[t] = ncmp;
    __syncthreads();
    for (int o = 64; o > 0; o >>= 1) {
        if (t < o) { sl[t] += sl[t + o]; sc[t] += sc[t + o]; }
        __syncthreads();
    }
    if (t == 0)
        out[0] = (sc[0] > 0) ? (float)(sl[0] / (double)sc[0]) : 0.0f;
}

extern "C" void kernel_launch(void* const* d_in, const int* in_sizes, int n_in,
                              void* d_out, int out_size) {
    const float* pred  = (const float*)d_in[0];
    const int*   attrs = (const int*)d_in[1];
    int B = in_sizes[0] / 8;
    if (B > MAX_B) B = MAX_B;
    int nchunk = (B + CHUNK - 1) / CHUNK;

    kA_count<<<nchunk, 256>>>(attrs, B);
    kB_scan<<<NBIN, 128>>>(nchunk);
    kB2_base<<<1, 128>>>();
    kSF<<<KSF_GRID, 32 * SWARPS>>>(pred, attrs, B, nchunk);
    k4_final<<<1, 128>>>((float*)d_out);
}

// round 14
// speedup vs baseline: 1.3006x; 1.3006x over previous
#include <cuda_runtime.h>

// AttributeBiasLoss — exact emulation of the reference's sequential fp32
// segment_sum (validated: rel_err 4.4e-6).
//   kA : fused per-node sigmoid-mean + per-chunk bin counts + flag reset
//        (full-chip parallel — R13 showed inlining sigmoid into scatter
//        starves the fold; keep it here)
//   kB : block-per-bin parallel scan of chunk counts -> [chunk][bin]
//   kB2: bin bases + ticket resets
//   kSF: SM-partitioned fused scatter + fold, occ 2, grid 296 (2 blocks on
//        every SM: 64 fold SMs -> exactly 128 fold blocks in wave 1).
//        Fold chain = 4-stage register pipeline (LDS issued 3 groups /
//        96 cyc ahead) to ride out prefetch-warp MIO bursts. Bit-exact.
//   k4 : fp32 means/diffs, final reduction

#define MAX_B      2097152
#define CHUNK      256
#define MAX_NCHUNK (MAX_B / CHUNK)   // 8192
#define NBIN       128
#define FOLD_SMS   64                // SMs reserved for fold chains
#define SWARPS     16                // warps per block
#define KSF_GRID   296               // 2 blocks/SM on 148 SMs
#define FOLD_BUF   4096              // floats per double-buffer half (16KB)

__device__ float    g_pernode[MAX_B];
__device__ float    g_sorted[MAX_B * 8];
__device__ unsigned g_counts[NBIN * MAX_NCHUNK];    // [bin][chunk]
__device__ unsigned g_chunkoff[MAX_NCHUNK * NBIN];  // [chunk][bin], bin-relative
__device__ unsigned g_flag[MAX_NCHUNK];
__device__ unsigned g_ticket;                        // scatter chunk ticket
__device__ unsigned g_fold_ticket;                   // fold bin ticket
__device__ unsigned g_bintotal[NBIN];
__device__ unsigned g_binbase[NBIN];
__device__ float    g_binmean[NBIN];

__device__ __forceinline__ float ref_sigmoid(float x) {
    float e = expf(-x);
    return __fdiv_rn(1.0f, __fadd_rn(1.0f, e));
}
__device__ __forceinline__ void st_release_flag(unsigned* p, unsigned v) {
    asm volatile("st.release.gpu.global.b32 [%0], %1;" :: "l"(p), "r"(v) : "memory");
}
__device__ __forceinline__ unsigned ld_acquire_flag(const unsigned* p) {
    unsigned v;
    asm volatile("ld.acquire.gpu.global.b32 %0, [%1];" : "=r"(v) : "l"(p) : "memory");
    return v;
}

// ---------------- kA: per-node mean + per-chunk counts + flag reset --------
__global__ void __launch_bounds__(256) kA_pernode_count(
    const float* __restrict__ pred, const int* __restrict__ attrs, int B)
{
    __shared__ unsigned cnt[NBIN];
    int tid = threadIdx.x;
    if (tid < NBIN) cnt[tid] = 0;
    if (tid == 0) g_flag[blockIdx.x] = 0;
    __syncthreads();

    int r = blockIdx.x * CHUNK + tid;
    if (r < B) {
        const float4* p = reinterpret_cast<const float4*>(pred + (size_t)r * 8);
        float4 p0 = __ldg(p), p1 = __ldg(p + 1);
        float s = ref_sigmoid(p0.x);
        s = __fadd_rn(s, ref_sigmoid(p0.y));
        s = __fadd_rn(s, ref_sigmoid(p0.z));
        s = __fadd_rn(s, ref_sigmoid(p0.w));
        s = __fadd_rn(s, ref_sigmoid(p1.x));
        s = __fadd_rn(s, ref_sigmoid(p1.y));
        s = __fadd_rn(s, ref_sigmoid(p1.z));
        s = __fadd_rn(s, ref_sigmoid(p1.w));
        g_pernode[r] = __fmul_rn(s, 0.125f);

        const int4* a = reinterpret_cast<const int4*>(attrs + (size_t)r * 8);
        int4 a0 = __ldg(a), a1 = __ldg(a + 1);
        atomicAdd(&cnt[  0 + a0.x], 1u);
        atomicAdd(&cnt[ 16 + a0.y], 1u);
        atomicAdd(&cnt[ 32 + a0.z], 1u);
        atomicAdd(&cnt[ 48 + a0.w], 1u);
        atomicAdd(&cnt[ 64 + a1.x], 1u);
        atomicAdd(&cnt[ 80 + a1.y], 1u);
        atomicAdd(&cnt[ 96 + a1.z], 1u);
        atomicAdd(&cnt[112 + a1.w], 1u);
    }
    __syncthreads();
    if (tid < NBIN)
        g_counts[(size_t)tid * MAX_NCHUNK + blockIdx.x] = cnt[tid];
}

// ---------------- kB: block-per-bin parallel scan ---------------------------
__global__ void __launch_bounds__(128) kB_scan(int nchunk) {
    int bin  = blockIdx.x;
    int t    = threadIdx.x;
    int lane = t & 31, wid = t >> 5;
    const unsigned* src = &g_counts[(size_t)bin * MAX_NCHUNK];
    __shared__ unsigned wsum[4];

    unsigned run = 0;
    for (int c0 = 0; c0 < nchunk; c0 += 128) {
        int c = c0 + t;
        unsigned v = (c < nchunk) ? src[c] : 0u;
        unsigned x = v;
        #pragma unroll
        for (int o = 1; o < 32; o <<= 1) {
            unsigned y = __shfl_up_sync(0xffffffffu, x, o);
            if (lane >= o) x += y;
        }
        if (lane == 31) wsum[wid] = x;
        __syncthreads();
        unsigned woff = 0;
        #pragma unroll
        for (int w = 0; w < 4; w++) if (w < wid) woff += wsum[w];
        if (c < nchunk)
            g_chunkoff[(size_t)c * NBIN + bin] = run + woff + x - v;
        unsigned btot = wsum[0] + wsum[1] + wsum[2] + wsum[3];
        __syncthreads();
        run += btot;
    }
    if (t == 0) g_bintotal[bin] = run;
}

// ---------------- kB2: bin bases + ticket resets -----------------------------
__global__ void __launch_bounds__(128) kB2_base() {
    int t    = threadIdx.x;
    int lane = t & 31, wid = t >> 5;
    __shared__ unsigned wsum[4];
    unsigned v = g_bintotal[t];
    unsigned x = v;
    #pragma unroll
    for (int o = 1; o < 32; o <<= 1) {
        unsigned y = __shfl_up_sync(0xffffffffu, x, o);
        if (lane >= o) x += y;
    }
    if (lane == 31) wsum[wid] = x;
    __syncthreads();
    unsigned woff = 0;
    #pragma unroll
    for (int w = 0; w < 4; w++) if (w < wid) woff += wsum[w];
    g_binbase[t] = woff + x - v;
    if (t == 0) { g_ticket = 0; g_fold_ticket = 0; }
}

// fold 8 values (two float4) into s, strict left-to-right fp32 order
#define FOLD8(A0, A1)                                          \
    do {                                                       \
        s = __fadd_rn(s, (A0).x); s = __fadd_rn(s, (A0).y);    \
        s = __fadd_rn(s, (A0).z); s = __fadd_rn(s, (A0).w);    \
        s = __fadd_rn(s, (A1).x); s = __fadd_rn(s, (A1).y);    \
        s = __fadd_rn(s, (A1).z); s = __fadd_rn(s, (A1).w);    \
    } while (0)

// ---------------- fold: one bin, executed by a whole block -------------------
__device__ void fold_bin(int bin, int nchunk, float (*buf)[FOLD_BUF])
{
    int tid  = threadIdx.x;
    int wid  = tid >> 5;
    int lane = tid & 31;

    unsigned n    = g_bintotal[bin];
    unsigned base = g_binbase[bin];
    int rounds = (int)((n + FOLD_BUF - 1) / FOLD_BUF);

    unsigned watermark = 0, ready = 0;  // prefetch-warp state

    if (wid == 1 && rounds > 0) {
        unsigned need = min(n, (unsigned)FOLD_BUF);
        while (ready < need) {
            int c = (int)watermark + lane;
            unsigned f = (c < nchunk) ? ld_acquire_flag(&g_flag[c]) : 1u;
            unsigned ball = __ballot_sync(0xffffffffu, f != 0);
            unsigned adv  = (ball == 0xffffffffu) ? 32u : (unsigned)(__ffs(~ball) - 1);
            if (adv == 0) { __nanosleep(128); continue; }
            watermark += adv;
            if ((int)watermark >= nchunk) { ready = n; break; }
            ready = g_chunkoff[(size_t)watermark * NBIN + bin];
        }
        #pragma unroll
        for (int j = 0; j < FOLD_BUF / 32; j++)
            buf[0][j * 32 + lane] = g_sorted[base + j * 32 + lane];
    }
    __syncthreads();

    float s = 0.0f;
    for (int r = 0; r < rounds; r++) {
        if (wid == 1) {
            if (r + 1 < rounds) {
                unsigned need = min(n, (unsigned)(r + 2) * FOLD_BUF);
                while (ready < need) {
                    int c = (int)watermark + lane;
                    unsigned f = (c < nchunk) ? ld_acquire_flag(&g_flag[c]) : 1u;
                    unsigned ball = __ballot_sync(0xffffffffu, f != 0);
                    unsigned adv  = (ball == 0xffffffffu) ? 32u : (unsigned)(__ffs(~ball) - 1);
                    if (adv == 0) { __nanosleep(128); continue; }
                    watermark += adv;
                    if ((int)watermark >= nchunk) { ready = n; break; }
                    ready = g_chunkoff[(size_t)watermark * NBIN + bin];
                }
                unsigned o = base + (unsigned)(r + 1) * FOLD_BUF;
                float* dst = buf[(r + 1) & 1];
                #pragma unroll
                for (int j = 0; j < FOLD_BUF / 32; j++)
                    dst[j * 32 + lane] = g_sorted[o + j * 32 + lane];
            }
        } else if (tid == 0) {
            // bit-exact serial fp32 chain; 4-stage pipeline: LDS issued three
            // 8-elem groups (96 cyc) ahead of consumption, no in-loop branches.
            const float4* b4 = reinterpret_cast<const float4*>(buf[r & 1]);
            const float*  bf = buf[r & 1];
            int cnt = min(FOLD_BUF, (int)(n - (unsigned)r * FOLD_BUF));
            int groups = cnt >> 3;
            int g = 0;
            if (groups >= 3) {
                float4 A0 = b4[0], A1 = b4[1];
                float4 B0 = b4[2], B1 = b4[3];
                float4 C0 = b4[4], C1 = b4[5];
                for (; g + 3 < groups; g++) {
                    float4 D0 = b4[2 * g + 6], D1 = b4[2 * g + 7];
                    FOLD8(A0, A1);
                    A0 = B0; A1 = B1; B0 = C0; B1 = C1; C0 = D0; C1 = D1;
                }
                FOLD8(A0, A1); g++;
                FOLD8(B0, B1); g++;
                FOLD8(C0, C1); g++;
            }
            for (int i = g * 8; i < cnt; i++) s = __fadd_rn(s, bf[i]);
        }
        __syncthreads();
    }
    if (tid == 0)
        g_binmean[bin] = (n > 0) ? __fdiv_rn(s, (float)n) : 0.0f;
    __syncthreads();
}

// ---------------- kSF: SM-partitioned scatter + fold -------------------------
__global__ void __launch_bounds__(32 * SWARPS, 2) kSF(
    const int* __restrict__ attrs, int B, int nchunk)
{
    __shared__ union {
        unsigned soff[SWARPS][NBIN];
        float    buf[2][FOLD_BUF];
    } sm;
    __shared__ int s_ticket;

    int tid  = threadIdx.x;
    int wid  = tid >> 5;
    int lane = tid & 31;

    unsigned smid;
    asm("mov.u32 %0, %%smid;" : "=r"(smid));

    if (smid < FOLD_SMS) {
        // ------------------- fold SM: claim a bin, fold it -------------------
        if (tid == 0) s_ticket = (int)atomicAdd(&g_fold_ticket, 1u);
        __syncthreads();
        int bin = s_ticket;
        if (bin < NBIN) fold_bin(bin, nchunk, sm.buf);
        return;
    }

    // ------------------- scatter SM: ticket-ordered chunks -------------------
    {
        unsigned* off = sm.soff[wid];
        for (;;) {
            int chunk = 0;
            if (lane == 0) chunk = (int)atomicAdd(&g_ticket, 1u);
            chunk = __shfl_sync(0xffffffffu, chunk, 0);
            if (chunk >= nchunk) break;

            for (int i = lane; i < NBIN; i += 32)
                off[i] = g_binbase[i] + g_chunkoff[(size_t)chunk * NBIN + i];
            __syncwarp();

            int start = chunk * CHUNK;
            #pragma unroll 1
            for (int s = 0; s < CHUNK / 32; s++) {
                int  r   = start + s * 32 + lane;
                bool act = (r < B);
                float pn = 0.f;
                int v[8];
                if (act) {
                    const int4* ap = reinterpret_cast<const int4*>(attrs + (size_t)r * 8);
                    int4 a0 = __ldg(ap), a1 = __ldg(ap + 1);
                    v[0] = a0.x; v[1] = a0.y; v[2] = a0.z; v[3] = a0.w;
                    v[4] = a1.x; v[5] = a1.y; v[6] = a1.z; v[7] = a1.w;
                    pn = g_pernode[r];
                } else {
                    #pragma unroll
                    for (int a = 0; a < 8; a++) v[a] = 16;
                }
                #pragma unroll
                for (int a = 0; a < 8; a++) {
                    unsigned mask   = __match_any_sync(0xffffffffu, v[a]);
                    unsigned rank   = __popc(mask & ((1u << lane) - 1u));
                    int      leader = __ffs(mask) - 1;
                    unsigned old    = 0;
                    if (lane == leader && v[a] < 16) {
                        int bin = a * 16 + v[a];
                        old = off[bin];
                        off[bin] = old + __popc(mask);
                    }
                    old = __shfl_sync(0xffffffffu, old, leader);
                    if (act) g_sorted[old + rank] = pn;
                }
                __syncwarp();
            }
            __threadfence();
            __syncwarp();
            if (lane == 0) st_release_flag(&g_flag[chunk], 1u);
        }
    }
    __syncthreads();

    // -------- safety net: fold any bins nobody on a fold SM claimed ----------
    for (;;) {
        if (tid == 0) s_ticket = (int)atomicAdd(&g_fold_ticket, 1u);
        __syncthreads();
        int bin = s_ticket;
        if (bin >= NBIN) break;
        fold_bin(bin, nchunk, sm.buf);
        __syncthreads();
    }
}

// ---------------- k4: pairwise squared diffs --------------------------------
__global__ void __launch_bounds__(128) k4_final(float* __restrict__ out) {
    __shared__ float  m[NBIN];
    __shared__ int    pres[NBIN];
    __shared__ double sl[128];
    __shared__ int    sc[128];
    int t = threadIdx.x;
    m[t]    = g_binmean[t];
    pres[t] = (g_bintotal[t] > 0);
    __syncthreads();
    double loss = 0.0;
    int    ncmp = 0;
    for (int idx = t; idx < 8 * 256; idx += 128) {
        int aa = idx >> 8, i = (idx >> 4) & 15, j = idx & 15;
        if (j > i) {
            int bi = aa * 16 + i, bj = aa * 16 + j;
            if (pres[bi] && pres[bj]) {
                float d  = __fsub_rn(m[bi], m[bj]);
                float dd = __fmul_rn(d, d);
                loss += (double)dd;
                ncmp += 1;
            }
        }
    }
    sl[t] = loss; sc[t] = ncmp;
    __syncthreads();
    for (int o = 64; o > 0; o >>= 1) {
        if (t < o) { sl[t] += sl[t + o]; sc[t] += sc[t + o]; }
        __syncthreads();
    }
    if (t == 0)
        out[0] = (sc[0] > 0) ? (float)(sl[0] / (double)sc[0]) : 0.0f;
}

extern "C" void kernel_launch(void* const* d_in, const int* in_sizes, int n_in,
                              void* d_out, int out_size) {
    const float* pred  = (const float*)d_in[0];
    const int*   attrs = (const int*)d_in[1];
    int B = in_sizes[0] / 8;
    if (B > MAX_B) B = MAX_B;
    int nchunk = (B + CHUNK - 1) / CHUNK;

    kA_pernode_count<<<nchunk, 256>>>(pred, attrs, B);
    kB_scan<<<NBIN, 128>>>(nchunk);
    kB2_base<<<1, 128>>>();
    kSF<<<KSF_GRID, 32 * SWARPS>>>(attrs, B, nchunk);
    k4_final<<<1, 128>>>((float*)d_out);
}